// round 3
// baseline (speedup 1.0000x reference)
#include <cuda_runtime.h>
#include <math.h>

#define Nn   50000
#define Ee   800000
#define ENb  (Ee + Nn)
#define Cc   128
#define Hh   4
#define Gg   512
#define OUTC 100
#define NEG  0.2f
#define EPSf 1e-16f

// ---- scratch (device globals: no allocations allowed) ----
__device__ __align__(16) float g_feat[Nn * Cc];   // layer output / next layer input
__device__ __align__(16) float g_h[Nn * Cc];      // transformed features (gather source)
__device__ __align__(16) float g_asrc[Nn * Hh];
__device__ __align__(16) float g_adst[Nn * Hh];
__device__ int   g_rowptr[Nn + 1];
__device__ int   g_cursor[Nn];
__device__ int   g_col[ENb];
__device__ __align__(16) float g_sums[Gg * Cc];
__device__ float g_cnt[Gg];

// ---------------- init: deg=1 (self loop), zero pool accumulators ----------------
__global__ void k_init() {
    int i = blockIdx.x * 256 + threadIdx.x;
    if (i < Gg * Cc) g_sums[i] = 0.f;
    if (i < Gg)      g_cnt[i]  = 0.f;
    if (i < Nn)      g_cursor[i] = 1;   // self loop counted
}

// ---------------- histogram over dst (edge_index staged as int32) ----------------
__global__ void k_hist(const int* __restrict__ ei) {
    int e = blockIdx.x * 256 + threadIdx.x;
    if (e < Ee) {
        int d = ei[Ee + e];
        atomicAdd(&g_cursor[d], 1);
    }
}

// ---------------- single-block exclusive scan (N=50000) ----------------
__global__ void k_scan() {
    __shared__ int s[1024];
    int t = threadIdx.x;
    const int PER = (Nn + 1023) / 1024;   // 49
    int base = t * PER;
    int sum = 0;
    for (int i = 0; i < PER; i++) {
        int idx = base + i;
        if (idx < Nn) sum += g_cursor[idx];
    }
    s[t] = sum;
    __syncthreads();
    // Hillis-Steele inclusive scan
    for (int o = 1; o < 1024; o <<= 1) {
        int u = (t >= o) ? s[t - o] : 0;
        __syncthreads();
        s[t] += u;
        __syncthreads();
    }
    int off = s[t] - sum;                 // exclusive prefix
    for (int i = 0; i < PER; i++) {
        int idx = base + i;
        if (idx < Nn) {
            int d = g_cursor[idx];
            g_rowptr[idx] = off;
            g_cursor[idx] = off;          // scatter cursor
            off += d;
        }
    }
    if (t == 1023) g_rowptr[Nn] = s[1023];
}

// ---------------- scatter edges + self loops into CSR ----------------
__global__ void k_scatter(const int* __restrict__ ei) {
    int e = blockIdx.x * 256 + threadIdx.x;
    if (e >= ENb) return;
    if (e < Ee) {
        int d = ei[Ee + e];
        int pos = atomicAdd(&g_cursor[d], 1);
        g_col[pos] = ei[e];
    } else {
        int n = e - Ee;
        int pos = atomicAdd(&g_cursor[n], 1);
        g_col[pos] = n;
    }
}

// ---------------- GEMM: g_h[N,128] = X[N,128] @ W[128,128]^T ----------------
// BM=128, BN=64, BK=32, 256 threads, each computes 8x4.
// FROM_GLOBAL: read input from g_feat instead of the X parameter.
template<bool FROM_GLOBAL>
__global__ __launch_bounds__(256) void k_gemm(const float* __restrict__ X,
                                              const float* __restrict__ W) {
    __shared__ __align__(16) float ftT[32][136];   // [k][row]
    __shared__ __align__(16) float wtT[32][72];    // [k][col]
    const float* __restrict__ src = FROM_GLOBAL ? (const float*)g_feat : X;
    int t = threadIdx.x;
    int rowBlk = blockIdx.x * 128;
    int colBlk = blockIdx.y * 64;
    int r0 = (t >> 4) << 3;          // 0..120
    int c0 = (t & 15) << 2;          // 0..60
    float acc[8][4];
#pragma unroll
    for (int j = 0; j < 8; j++)
#pragma unroll
        for (int l = 0; l < 4; l++) acc[j][l] = 0.f;

    for (int kb = 0; kb < 128; kb += 32) {
#pragma unroll
        for (int i = 0; i < 16; i++) {
            int idx = t + i * 256;
            int r = idx >> 5, k = idx & 31;
            int row = rowBlk + r;
            ftT[k][r] = (row < Nn) ? src[row * 128 + kb + k] : 0.f;
        }
#pragma unroll
        for (int i = 0; i < 8; i++) {
            int idx = t + i * 256;
            int c = idx >> 5, k = idx & 31;
            wtT[k][c] = W[(colBlk + c) * 128 + kb + k];
        }
        __syncthreads();
#pragma unroll
        for (int k = 0; k < 32; k++) {
            float4 b  = *(const float4*)&wtT[k][c0];
            float4 a0 = *(const float4*)&ftT[k][r0];
            float4 a1 = *(const float4*)&ftT[k][r0 + 4];
            float av[8] = {a0.x, a0.y, a0.z, a0.w, a1.x, a1.y, a1.z, a1.w};
#pragma unroll
            for (int j = 0; j < 8; j++) {
                acc[j][0] = fmaf(av[j], b.x, acc[j][0]);
                acc[j][1] = fmaf(av[j], b.y, acc[j][1]);
                acc[j][2] = fmaf(av[j], b.z, acc[j][2]);
                acc[j][3] = fmaf(av[j], b.w, acc[j][3]);
            }
        }
        __syncthreads();
    }
#pragma unroll
    for (int j = 0; j < 8; j++) {
        int row = rowBlk + r0 + j;
        if (row < Nn) {
            float4 v = make_float4(acc[j][0], acc[j][1], acc[j][2], acc[j][3]);
            *(float4*)&g_h[row * 128 + colBlk + c0] = v;
        }
    }
}

// ---------------- attention logits: a_src/a_dst [N,H] from g_h ----------------
__global__ void k_att(const float* __restrict__ AS,
                      const float* __restrict__ AD) {
    int i = blockIdx.x * 256 + threadIdx.x;
    if (i >= Nn * Hh) return;
    int n = i >> 2, h = i & 3;
    const float4* hv  = (const float4*)(g_h + n * 128 + h * 32);
    const float4* asv = (const float4*)(AS + h * 32);
    const float4* adv = (const float4*)(AD + h * 32);
    float s = 0.f, d = 0.f;
#pragma unroll
    for (int j = 0; j < 8; j++) {
        float4 v = hv[j], a = asv[j], b = adv[j];
        s += v.x * a.x + v.y * a.y + v.z * a.z + v.w * a.w;
        d += v.x * b.x + v.y * b.y + v.z * b.z + v.w * b.w;
    }
    g_asrc[i] = s;
    g_adst[i] = d;
}

__device__ __forceinline__ float lrelu(float x) { return x > 0.f ? x : NEG * x; }

// ---------------- per-dst-node fused softmax + aggregation (1 warp / node) ----------------
// reads g_h / g_asrc / g_adst / CSR, writes ELU result to g_feat
__global__ __launch_bounds__(256) void k_agg(const float* __restrict__ bias) {
    int n = (blockIdx.x * 256 + threadIdx.x) >> 5;
    int lane = threadIdx.x & 31;
    if (n >= Nn) return;
    int start = g_rowptr[n], end = g_rowptr[n + 1];
    int head = lane >> 3;
    int ch = lane << 2;
    float4 ad4 = *(const float4*)(g_adst + n * 4);

    // pass 1: per-head max of leaky_relu(a_src[s]+a_dst[n])
    float4 mx = make_float4(-1e30f, -1e30f, -1e30f, -1e30f);
    for (int e = start + lane; e < end; e += 32) {
        int s = g_col[e];
        float4 a = *(const float4*)(g_asrc + s * 4);
        mx.x = fmaxf(mx.x, lrelu(a.x + ad4.x));
        mx.y = fmaxf(mx.y, lrelu(a.y + ad4.y));
        mx.z = fmaxf(mx.z, lrelu(a.z + ad4.z));
        mx.w = fmaxf(mx.w, lrelu(a.w + ad4.w));
    }
#pragma unroll
    for (int o = 16; o; o >>= 1) {
        mx.x = fmaxf(mx.x, __shfl_xor_sync(0xffffffffu, mx.x, o));
        mx.y = fmaxf(mx.y, __shfl_xor_sync(0xffffffffu, mx.y, o));
        mx.z = fmaxf(mx.z, __shfl_xor_sync(0xffffffffu, mx.z, o));
        mx.w = fmaxf(mx.w, __shfl_xor_sync(0xffffffffu, mx.w, o));
    }
    float m   = (head == 0) ? mx.x : (head == 1) ? mx.y : (head == 2) ? mx.z : mx.w;
    float adh = (head == 0) ? ad4.x : (head == 1) ? ad4.y : (head == 2) ? ad4.z : ad4.w;

    // pass 2: unnormalized weighted sum + denominator (2-edge unroll for MLP)
    float4 acc = make_float4(0.f, 0.f, 0.f, 0.f);
    float den = 0.f;
    int e = start;
    for (; e + 1 < end; e += 2) {
        int s0 = g_col[e], s1 = g_col[e + 1];
        float a0 = g_asrc[(s0 << 2) + head] + adh;
        float a1 = g_asrc[(s1 << 2) + head] + adh;
        float4 h0 = *(const float4*)(g_h + s0 * 128 + ch);
        float4 h1 = *(const float4*)(g_h + s1 * 128 + ch);
        float w0 = __expf(lrelu(a0) - m);
        float w1 = __expf(lrelu(a1) - m);
        den += w0 + w1;
        acc.x += w0 * h0.x + w1 * h1.x;
        acc.y += w0 * h0.y + w1 * h1.y;
        acc.z += w0 * h0.z + w1 * h1.z;
        acc.w += w0 * h0.w + w1 * h1.w;
    }
    if (e < end) {
        int s0 = g_col[e];
        float a0 = g_asrc[(s0 << 2) + head] + adh;
        float4 h0 = *(const float4*)(g_h + s0 * 128 + ch);
        float w0 = __expf(lrelu(a0) - m);
        den += w0;
        acc.x += w0 * h0.x;
        acc.y += w0 * h0.y;
        acc.z += w0 * h0.z;
        acc.w += w0 * h0.w;
    }
    float inv = 1.f / (den + EPSf);
    float4 b4 = *(const float4*)(bias + ch);
    float vx = acc.x * inv + b4.x;
    float vy = acc.y * inv + b4.y;
    float vz = acc.z * inv + b4.z;
    float vw = acc.w * inv + b4.w;
    // ELU
    vx = vx > 0.f ? vx : expm1f(vx);
    vy = vy > 0.f ? vy : expm1f(vy);
    vz = vz > 0.f ? vz : expm1f(vz);
    vw = vw > 0.f ? vw : expm1f(vw);
    *(float4*)&g_feat[n * 128 + ch] = make_float4(vx, vy, vz, vw);
}

// ---------------- global mean pool (atomics over g_feat; batch staged as int32) ----------------
__global__ __launch_bounds__(256) void k_pool(const int* __restrict__ batch) {
    int n = (blockIdx.x * 256 + threadIdx.x) >> 5;
    int lane = threadIdx.x & 31;
    if (n >= Nn) return;
    int g = batch[n];
    float4 v = *(const float4*)(g_feat + n * 128 + (lane << 2));
    float* sp = &g_sums[g * 128 + (lane << 2)];
    atomicAdd(sp + 0, v.x);
    atomicAdd(sp + 1, v.y);
    atomicAdd(sp + 2, v.z);
    atomicAdd(sp + 3, v.w);
    if (lane == 0) atomicAdd(&g_cnt[g], 1.f);
}

// ---------------- final FC: out[G,100] = (sums/cnt) @ fcW^T + fcb ----------------
__global__ void k_fc(const float* __restrict__ fcW,
                     const float* __restrict__ fcb,
                     float* __restrict__ out) {
    int i = blockIdx.x * 256 + threadIdx.x;
    if (i >= Gg * OUTC) return;
    int g = i / OUTC, o = i - g * OUTC;
    float inv = 1.f / fmaxf(g_cnt[g], 1.f);
    const float* sr = &g_sums[g * 128];
    const float* wr = &fcW[o * 128];
    float s = 0.f;
#pragma unroll
    for (int c = 0; c < 128; c++) s = fmaf(sr[c], wr[c], s);
    out[i] = s * inv + fcb[o];
}

extern "C" void kernel_launch(void* const* d_in, const int* in_sizes, int n_in,
                              void* d_out, int out_size) {
    const float* x     = (const float*)d_in[0];
    const int*   ei    = (const int*)d_in[1];    // int64 in reference -> staged int32
    const int*   batch = (const int*)d_in[2];    // int64 in reference -> staged int32
    const float* W1 = (const float*)d_in[3];
    const float* as1 = (const float*)d_in[4];
    const float* ad1 = (const float*)d_in[5];
    const float* b1 = (const float*)d_in[6];
    const float* W2 = (const float*)d_in[7];
    const float* as2 = (const float*)d_in[8];
    const float* ad2 = (const float*)d_in[9];
    const float* b2 = (const float*)d_in[10];
    const float* W3 = (const float*)d_in[11];
    const float* as3 = (const float*)d_in[12];
    const float* ad3 = (const float*)d_in[13];
    const float* b3 = (const float*)d_in[14];
    const float* fcW = (const float*)d_in[15];
    const float* fcb = (const float*)d_in[16];
    float* out = (float*)d_out;

    // CSR build (once per call) + pool accumulator zeroing
    k_init<<<256, 256>>>();
    k_hist<<<(Ee + 255) / 256, 256>>>(ei);
    k_scan<<<1, 1024>>>();
    k_scatter<<<(ENb + 255) / 256, 256>>>(ei);

    dim3 gg((Nn + 127) / 128, 2);
    int aggBlocks = (Nn + 7) / 8;
    int attBlocks = (Nn * Hh + 255) / 256;

    // layer 1
    k_gemm<false><<<gg, 256>>>(x, W1);
    k_att<<<attBlocks, 256>>>(as1, ad1);
    k_agg<<<aggBlocks, 256>>>(b1);
    // layer 2
    k_gemm<true><<<gg, 256>>>(nullptr, W2);
    k_att<<<attBlocks, 256>>>(as2, ad2);
    k_agg<<<aggBlocks, 256>>>(b2);
    // layer 3
    k_gemm<true><<<gg, 256>>>(nullptr, W3);
    k_att<<<attBlocks, 256>>>(as3, ad3);
    k_agg<<<aggBlocks, 256>>>(b3);

    // pool + fc
    k_pool<<<aggBlocks, 256>>>(batch);
    k_fc<<<(Gg * OUTC + 255) / 256, 256>>>(fcW, fcb, out);
}